// round 1
// baseline (speedup 1.0000x reference)
#include <cuda_runtime.h>
#include <cstdint>
#include <cstddef>

#define DIM     4096
#define HDIM    128
#define NHEADS  32
#define BSZ     2
#define SEQ     1024
#define CACHE   1024
#define TKV     2048
#define MROWS   2048   // BSZ*SEQ

// ---------------- scratch (static device memory; no allocations allowed) ----
static __device__ float g_q  [(size_t)MROWS * DIM];
static __device__ float g_k  [(size_t)MROWS * DIM];
static __device__ float g_v  [(size_t)MROWS * DIM];
static __device__ float g_ctx[(size_t)MROWS * DIM];
static __device__ float g_sc [(size_t)BSZ * NHEADS * SEQ * TKV];   // 512MB

// ---------------- tf32 helpers ----------------------------------------------
__device__ __forceinline__ uint32_t f2tf(float x) {
    uint32_t r;
    asm("cvt.rna.tf32.f32 %0, %1;" : "=r"(r) : "f"(x));
    return r;
}

__device__ __forceinline__ void mma_m16n8k8(float c[4], const uint32_t a[4],
                                            const uint32_t b[2]) {
    asm volatile(
        "mma.sync.aligned.m16n8k8.row.col.f32.tf32.tf32.f32 "
        "{%0,%1,%2,%3},{%4,%5,%6,%7},{%8,%9},{%0,%1,%2,%3};\n"
        : "+f"(c[0]), "+f"(c[1]), "+f"(c[2]), "+f"(c[3])
        : "r"(a[0]), "r"(a[1]), "r"(a[2]), "r"(a[3]),
          "r"(b[0]), "r"(b[1]));
}

// ---------------- batched TF32 GEMM -----------------------------------------
// C[M,N] = A[M,K] * op(B)    op(B) = B[N,K]^T if NT, else B[K,N]
// Block tile 128x128x16, 256 threads (8 warps, 4(M) x 2(N)), warp tile 32x64.
// Batch index z -> (b = z/nH, h = z%nH); per-operand offset b*s?b + h*s?h.
// All problem dims are exact multiples of the tiles (asserted by construction).
template <bool NT>
__global__ __launch_bounds__(256) void gemm_tf32(
    const float* __restrict__ Ag, const float* __restrict__ Bg,
    float* __restrict__ Cg, int K, int lda, int ldb, int ldc,
    long long sAb, long long sAh, long long sBb, long long sBh,
    long long sCb, long long sCh, int nH)
{
    const int z  = blockIdx.z;
    const int bb = z / nH, hh = z - bb * nH;
    const float* A = Ag + (size_t)bb * sAb + (size_t)hh * sAh;
    const float* B = Bg + (size_t)bb * sBb + (size_t)hh * sBh;
    float*       C = Cg + (size_t)bb * sCb + (size_t)hh * sCh;

    const int m0 = blockIdx.y << 7;
    const int n0 = blockIdx.x << 7;

    // padded layouts: row stride 20 words makes the fragment reads
    // (m = off + groupID, k = lane&3 [+4]) hit 32 distinct banks.
    __shared__ uint32_t sA[2][128][20];
    __shared__ uint32_t sB[2][128][20];

    const int tid  = threadIdx.x;
    const int lane = tid & 31, w = tid >> 5;
    const int wm = (w & 3) << 5;      // warp M offset (0,32,64,96)
    const int wn = (w >> 2) << 6;     // warp N offset (0,64)
    const int g  = lane >> 2, t = lane & 3;

    float acc[2][8][4];
#pragma unroll
    for (int i = 0; i < 2; i++)
#pragma unroll
        for (int j = 0; j < 8; j++)
#pragma unroll
            for (int l = 0; l < 4; l++) acc[i][j][l] = 0.f;

    const int alr = tid >> 2;           // 0..63
    const int alc = (tid & 3) << 2;     // 0,4,8,12
    const int nkr = tid >> 5;           // 0..7   (NN loader)
    const int nnc = (tid & 31) << 2;    // 0..124 (NN loader)

    float4 ra0, ra1, rb0, rb1;

#define GLOAD(k0)                                                              \
    do {                                                                       \
        ra0 = *(const float4*)(A + (size_t)(m0 + alr)      * lda + (k0) + alc);\
        ra1 = *(const float4*)(A + (size_t)(m0 + alr + 64) * lda + (k0) + alc);\
        if (NT) {                                                              \
            rb0 = *(const float4*)(B + (size_t)(n0 + alr)      * ldb + (k0) + alc); \
            rb1 = *(const float4*)(B + (size_t)(n0 + alr + 64) * ldb + (k0) + alc); \
        } else {                                                               \
            rb0 = *(const float4*)(B + (size_t)((k0) + nkr)     * ldb + n0 + nnc);  \
            rb1 = *(const float4*)(B + (size_t)((k0) + nkr + 8) * ldb + n0 + nnc);  \
        }                                                                      \
    } while (0)

#define SSTORE(buf)                                                            \
    do {                                                                       \
        sA[buf][alr][alc + 0] = f2tf(ra0.x);                                   \
        sA[buf][alr][alc + 1] = f2tf(ra0.y);                                   \
        sA[buf][alr][alc + 2] = f2tf(ra0.z);                                   \
        sA[buf][alr][alc + 3] = f2tf(ra0.w);                                   \
        sA[buf][alr + 64][alc + 0] = f2tf(ra1.x);                              \
        sA[buf][alr + 64][alc + 1] = f2tf(ra1.y);                              \
        sA[buf][alr + 64][alc + 2] = f2tf(ra1.z);                              \
        sA[buf][alr + 64][alc + 3] = f2tf(ra1.w);                              \
        if (NT) {                                                              \
            sB[buf][alr][alc + 0] = f2tf(rb0.x);                               \
            sB[buf][alr][alc + 1] = f2tf(rb0.y);                               \
            sB[buf][alr][alc + 2] = f2tf(rb0.z);                               \
            sB[buf][alr][alc + 3] = f2tf(rb0.w);                               \
            sB[buf][alr + 64][alc + 0] = f2tf(rb1.x);                          \
            sB[buf][alr + 64][alc + 1] = f2tf(rb1.y);                          \
            sB[buf][alr + 64][alc + 2] = f2tf(rb1.z);                          \
            sB[buf][alr + 64][alc + 3] = f2tf(rb1.w);                          \
        } else {                                                               \
            sB[buf][nnc + 0][nkr] = f2tf(rb0.x);                               \
            sB[buf][nnc + 1][nkr] = f2tf(rb0.y);                               \
            sB[buf][nnc + 2][nkr] = f2tf(rb0.z);                               \
            sB[buf][nnc + 3][nkr] = f2tf(rb0.w);                               \
            sB[buf][nnc + 0][nkr + 8] = f2tf(rb1.x);                           \
            sB[buf][nnc + 1][nkr + 8] = f2tf(rb1.y);                           \
            sB[buf][nnc + 2][nkr + 8] = f2tf(rb1.z);                           \
            sB[buf][nnc + 3][nkr + 8] = f2tf(rb1.w);                           \
        }                                                                      \
    } while (0)

    GLOAD(0);
    SSTORE(0);
    __syncthreads();

    const int ntiles = K >> 4;
    int cur = 0;
    for (int tile = 0; tile < ntiles; ++tile) {
        if (tile + 1 < ntiles) {
            GLOAD((tile + 1) << 4);
        }
#pragma unroll
        for (int kk = 0; kk < 16; kk += 8) {
            uint32_t af[2][4], bf[8][2];
#pragma unroll
            for (int mt = 0; mt < 2; mt++) {
                const int mr = wm + (mt << 4) + g;
                af[mt][0] = sA[cur][mr][kk + t];
                af[mt][1] = sA[cur][mr + 8][kk + t];
                af[mt][2] = sA[cur][mr][kk + t + 4];
                af[mt][3] = sA[cur][mr + 8][kk + t + 4];
            }
#pragma unroll
            for (int nt = 0; nt < 8; nt++) {
                const int nr = wn + (nt << 3) + g;
                bf[nt][0] = sB[cur][nr][kk + t];
                bf[nt][1] = sB[cur][nr][kk + t + 4];
            }
#pragma unroll
            for (int mt = 0; mt < 2; mt++)
#pragma unroll
                for (int nt = 0; nt < 8; nt++)
                    mma_m16n8k8(acc[mt][nt], af[mt], bf[nt]);
        }
        if (tile + 1 < ntiles) {
            const int nb = cur ^ 1;
            SSTORE(nb);
            __syncthreads();
            cur = nb;
        }
    }

#pragma unroll
    for (int mt = 0; mt < 2; mt++) {
#pragma unroll
        for (int nt = 0; nt < 8; nt++) {
            const int row = m0 + wm + (mt << 4) + g;
            const int col = n0 + wn + (nt << 3) + (t << 1);
            float2 v0; v0.x = acc[mt][nt][0]; v0.y = acc[mt][nt][1];
            float2 v1; v1.x = acc[mt][nt][2]; v1.y = acc[mt][nt][3];
            *(float2*)(C + (size_t)row * ldc + col)       = v0;
            *(float2*)(C + (size_t)(row + 8) * ldc + col) = v1;
        }
    }
#undef GLOAD
#undef SSTORE
}

// ---------------- RoPE on q (in place) and k -> xk; v -> xv -----------------
// One thread per (b, s, h, j) pair of elements.
__global__ void rope_scatter(float* __restrict__ q, const float* __restrict__ k,
                             const float* __restrict__ v,
                             const float* __restrict__ rope,
                             float* __restrict__ xk, float* __restrict__ xv)
{
    const size_t idx = (size_t)blockIdx.x * 256 + threadIdx.x; // < 4194304
    const int j = (int)(idx & 63);
    const int h = (int)((idx >> 6) & 31);
    const int s = (int)((idx >> 11) & 1023);
    const int b = (int)(idx >> 21);

    const size_t src = ((size_t)(b * SEQ + s)) * DIM + h * HDIM + 2 * j;
    const float c  = rope[(size_t)(s * 64 + j) * 2];
    const float sn = rope[(size_t)(s * 64 + j) * 2 + 1];

    const float q0 = q[src], q1 = q[src + 1];
    q[src]     = q0 * c - q1 * sn;
    q[src + 1] = q0 * sn + q1 * c;

    const float k0 = k[src], k1 = k[src + 1];
    const size_t dst = (((size_t)(b * NHEADS + h)) * TKV + CACHE + s) * HDIM + 2 * j;
    xk[dst]     = k0 * c - k1 * sn;
    xk[dst + 1] = k0 * sn + k1 * c;

    xv[dst]     = v[src];
    xv[dst + 1] = v[src + 1];
}

// ---------------- copy k_cache/v_cache into xk/xv[:, :, 0:CACHE, :] ---------
__global__ void cache_copy(const float* __restrict__ kc,
                           const float* __restrict__ vc,
                           float* __restrict__ xk, float* __restrict__ xv)
{
    const size_t i4  = (size_t)blockIdx.x * 256 + threadIdx.x; // < 2097152
    const size_t src = i4 * 4;
    const size_t bh  = src >> 17;              // / (CACHE*HDIM)
    const size_t dst = src + bh * (size_t)(CACHE * HDIM);
    *(float4*)(xk + dst) = *(const float4*)(kc + src);
    *(float4*)(xv + dst) = *(const float4*)(vc + src);
}

// ---------------- causal softmax over scores rows ---------------------------
__global__ void softmax_causal(float* __restrict__ S)
{
    const int s  = blockIdx.x;
    const int bh = blockIdx.y;
    float* row = S + ((size_t)bh * SEQ + s) * TKV;
    const int L = CACHE + s + 1;
    const int tid = threadIdx.x;
    const float scale = 0.08838834764831845f; // 1/sqrt(128)

    float v[8];
    float m = -3.0e38f;
#pragma unroll
    for (int i = 0; i < 8; i++) {
        const int idx = tid + (i << 8);
        v[i] = (idx < L) ? row[idx] : -3.0e38f;
        m = fmaxf(m, v[i]);
    }
    __shared__ float red[8];
#pragma unroll
    for (int o = 16; o > 0; o >>= 1) m = fmaxf(m, __shfl_xor_sync(0xffffffffu, m, o));
    if ((tid & 31) == 0) red[tid >> 5] = m;
    __syncthreads();
    float bm = red[0];
#pragma unroll
    for (int i = 1; i < 8; i++) bm = fmaxf(bm, red[i]);

    float sum = 0.f;
#pragma unroll
    for (int i = 0; i < 8; i++) {
        const int idx = tid + (i << 8);
        if (idx < L) { v[i] = __expf(scale * (v[i] - bm)); sum += v[i]; }
        else         { v[i] = 0.f; }
    }
#pragma unroll
    for (int o = 16; o > 0; o >>= 1) sum += __shfl_xor_sync(0xffffffffu, sum, o);
    __syncthreads();
    if ((tid & 31) == 0) red[tid >> 5] = sum;
    __syncthreads();
    float bs = 0.f;
#pragma unroll
    for (int i = 0; i < 8; i++) bs += red[i];
    const float inv = 1.f / bs;
#pragma unroll
    for (int i = 0; i < 8; i++) row[tid + (i << 8)] = v[i] * inv;
}

// ---------------- launch -----------------------------------------------------
extern "C" void kernel_launch(void* const* d_in, const int* in_sizes, int n_in,
                              void* d_out, int out_size)
{
    const float* x    = (const float*)d_in[0];
    const float* kc   = (const float*)d_in[1];
    const float* vc   = (const float*)d_in[2];
    const float* rope = (const float*)d_in[3];
    const float* Wq   = (const float*)d_in[4];
    const float* Wk   = (const float*)d_in[5];
    const float* Wv   = (const float*)d_in[6];
    const float* Wo   = (const float*)d_in[7];

    float* out = (float*)d_out;
    float* xk  = out + (size_t)BSZ * SEQ * DIM;               // +8388608
    float* xv  = xk + (size_t)BSZ * NHEADS * TKV * HDIM;      // +16777216

    float *q, *k, *v, *ctx, *sc;
    cudaGetSymbolAddress((void**)&q,   g_q);
    cudaGetSymbolAddress((void**)&k,   g_k);
    cudaGetSymbolAddress((void**)&v,   g_v);
    cudaGetSymbolAddress((void**)&ctx, g_ctx);
    cudaGetSymbolAddress((void**)&sc,  g_sc);

    const dim3 blk(256);

    // Q/K/V projections: C[2048,4096] = x[2048,4096] * W^T
    const dim3 gp(DIM / 128, MROWS / 128, 1);
    gemm_tf32<true><<<gp, blk>>>(x, Wq, q, DIM, DIM, DIM, DIM,
                                 0, 0, 0, 0, 0, 0, 1);
    gemm_tf32<true><<<gp, blk>>>(x, Wk, k, DIM, DIM, DIM, DIM,
                                 0, 0, 0, 0, 0, 0, 1);
    gemm_tf32<true><<<gp, blk>>>(x, Wv, v, DIM, DIM, DIM, DIM,
                                 0, 0, 0, 0, 0, 0, 1);

    cache_copy<<<8192, blk>>>(kc, vc, xk, xv);
    rope_scatter<<<16384, blk>>>(q, k, v, rope, xk, xv);

    // scores[b,h,s,t] = q[b,h,s,:] . xk[b,h,t,:]
    const dim3 gs(TKV / 128, SEQ / 128, BSZ * NHEADS);
    gemm_tf32<true><<<gs, blk>>>(
        q, xk, sc, HDIM, DIM, HDIM, TKV,
        (long long)SEQ * DIM, HDIM,
        (long long)NHEADS * TKV * HDIM, (long long)TKV * HDIM,
        (long long)NHEADS * SEQ * TKV, (long long)SEQ * TKV, NHEADS);

    const dim3 gsm(SEQ, BSZ * NHEADS);
    softmax_causal<<<gsm, blk>>>(sc);

    // ctx[b,s,h,:] = P[b,h,s,:] @ xv[b,h,:,:]   (NN)
    const dim3 gpv(HDIM / 128, SEQ / 128, BSZ * NHEADS);
    gemm_tf32<false><<<gpv, blk>>>(
        sc, xv, ctx, TKV, TKV, HDIM, DIM,
        (long long)NHEADS * SEQ * TKV, (long long)SEQ * TKV,
        (long long)NHEADS * TKV * HDIM, (long long)TKV * HDIM,
        (long long)SEQ * DIM, HDIM, NHEADS);

    // output = ctx @ Wo^T
    gemm_tf32<true><<<gp, blk>>>(ctx, Wo, out, DIM, DIM, DIM, DIM,
                                 0, 0, 0, 0, 0, 0, 1);
}

// round 3
// speedup vs baseline: 1.2946x; 1.2946x over previous
#include <cuda_runtime.h>
#include <cstdint>
#include <cstddef>

#define DIM     4096
#define HDIM    128
#define NHEADS  32
#define BSZ     2
#define SEQ     1024
#define CACHE   1024
#define TKV     2048
#define MROWS   2048   // BSZ*SEQ

// ---------------- scratch (static device memory; no allocations allowed) ----
static __device__ float g_xr [(size_t)MROWS * DIM];                 // 32MB  rounded x
static __device__ float g_wq [(size_t)DIM * DIM];                  // 64MB  rounded Wq
static __device__ float g_wk [(size_t)DIM * DIM];                  // 64MB
static __device__ float g_wv [(size_t)DIM * DIM];                  // 64MB
static __device__ float g_wo [(size_t)DIM * DIM];                  // 64MB
static __device__ float g_q  [(size_t)MROWS * DIM];                 // 32MB  q (roped+rounded)
static __device__ float g_k  [(size_t)MROWS * DIM];                 // 32MB  raw k proj
static __device__ float g_v  [(size_t)MROWS * DIM];                 // 32MB  raw v proj
static __device__ float g_ctx[(size_t)MROWS * DIM];                 // 32MB  rounded ctx
static __device__ float g_kr [(size_t)BSZ * NHEADS * TKV * HDIM];   // 64MB  rounded xk copy
static __device__ float g_vt [(size_t)BSZ * NHEADS * HDIM * TKV];   // 64MB  rounded v^T
static __device__ float g_sc [(size_t)BSZ * NHEADS * SEQ * TKV];    // 512MB scores/probs

// ---------------- helpers -----------------------------------------------------
__device__ __forceinline__ uint32_t f2tf(float x) {
    uint32_t r;
    asm("cvt.rna.tf32.f32 %0, %1;" : "=r"(r) : "f"(x));
    return r;
}
__device__ __forceinline__ float f2tff(float x) {
    return __uint_as_float(f2tf(x));
}

__device__ __forceinline__ uint32_t smem_u32(const void* p) {
    uint32_t a;
    asm("{ .reg .u64 t; cvta.to.shared.u64 t, %1; cvt.u32.u64 %0, t; }"
        : "=r"(a) : "l"(p));
    return a;
}

__device__ __forceinline__ void cp16(uint32_t dst, const float* src) {
    asm volatile("cp.async.cg.shared.global [%0], [%1], 16;"
                 :: "r"(dst), "l"(src));
}
#define CP_COMMIT() asm volatile("cp.async.commit_group;" ::: "memory")
#define CP_WAIT1()  asm volatile("cp.async.wait_group 1;"  ::: "memory")

__device__ __forceinline__ void mma_m16n8k8(float c[4], const uint32_t a[4],
                                            const uint32_t b[2]) {
    asm volatile(
        "mma.sync.aligned.m16n8k8.row.col.f32.tf32.tf32.f32 "
        "{%0,%1,%2,%3},{%4,%5,%6,%7},{%8,%9},{%0,%1,%2,%3};\n"
        : "+f"(c[0]), "+f"(c[1]), "+f"(c[2]), "+f"(c[3])
        : "r"(a[0]), "r"(a[1]), "r"(a[2]), "r"(a[3]),
          "r"(b[0]), "r"(b[1]));
}

// ---------------- pipelined TF32 NT GEMM --------------------------------------
// C[M,N] = A[M,K] * B[N,K]^T.  A/B hold tf32-rounded bits (no cvt inside).
// Block 128x128, K-chunk 32, 3-stage cp.async pipeline, 256 thr (8 warps 4x2).
// causal: skip block if n0 >= CACHE + m0 + 128 (scores).
// kcap:   clamp K to CACHE + m0 + 128 (PV; tail of A is exact zeros).
// round_out: tf32-round C values at store (for internal tensors).
__global__ __launch_bounds__(256, 2) void gemm_tc(
    const float* __restrict__ Ag, const float* __restrict__ Bg,
    float* __restrict__ Cg, int K, int lda, int ldb, int ldc,
    long long sAb, long long sAh, long long sBb, long long sBh,
    long long sCb, long long sCh, int nH,
    int causal, int kcap, int round_out)
{
    constexpr int RS  = 36;            // smem row stride in words (conflict-free)
    constexpr int TW  = 128 * RS;      // words per matrix tile (4608)
    constexpr int SW  = 2 * TW;        // words per stage (9216)
    constexpr int SWB = SW * 4;        // stage bytes (36864)
    extern __shared__ float smem[];

    const int z  = blockIdx.z;
    const int bb = z / nH, hh = z - bb * nH;
    const float* A = Ag + (size_t)bb * sAb + (size_t)hh * sAh;
    const float* B = Bg + (size_t)bb * sBb + (size_t)hh * sBh;
    float*       C = Cg + (size_t)bb * sCb + (size_t)hh * sCh;
    const int m0 = blockIdx.y << 7;
    const int n0 = blockIdx.x << 7;

    if (causal && n0 >= CACHE + m0 + 128) return;
    int Keff = K;
    if (kcap) { const int cap = CACHE + m0 + 128; if (cap < K) Keff = cap; }
    const int nt = Keff >> 5;

    const int tid  = threadIdx.x;
    const int lane = tid & 31, w = tid >> 5;
    const int wm = (w & 3) << 5;       // warp M offset
    const int wn = (w >> 2) << 6;      // warp N offset
    const int g  = lane >> 2, tq = lane & 3;

    // per-thread cp.async bases: 4 rows (stride 32) x one 16B chunk each matrix
    const int crow = tid >> 3;                 // 0..31
    const int cch  = (tid & 7) << 2;           // word col 0,4,...,28
    const float* aP = A + (size_t)(m0 + crow) * lda + cch;
    const float* bP = B + (size_t)(n0 + crow) * ldb + cch;
    const uint32_t sb = smem_u32(smem);
    const uint32_t dA = sb + (uint32_t)((crow * RS + cch) << 2);
    const uint32_t dB = dA + (uint32_t)(TW << 2);

    float acc[2][8][4];
#pragma unroll
    for (int i = 0; i < 2; i++)
#pragma unroll
        for (int j = 0; j < 8; j++)
#pragma unroll
            for (int l = 0; l < 4; l++) acc[i][j][l] = 0.f;

#define ISSUE(SOFF, T) do {                                                    \
    const int _k0 = (T) << 5;                                                  \
    _Pragma("unroll")                                                          \
    for (int _i = 0; _i < 4; _i++) {                                           \
        cp16(dA + (SOFF) + (uint32_t)(_i * (32 * RS * 4)),                     \
             aP + _k0 + (size_t)(_i * 32) * lda);                              \
        cp16(dB + (SOFF) + (uint32_t)(_i * (32 * RS * 4)),                     \
             bP + _k0 + (size_t)(_i * 32) * ldb);                              \
    }                                                                          \
} while (0)

#define COMPUTE(BUF) do {                                                      \
    const uint32_t* sA  = (const uint32_t*)smem + (BUF) * SW;                  \
    const uint32_t* sBp = sA + TW;                                             \
    _Pragma("unroll")                                                          \
    for (int kk = 0; kk < 32; kk += 8) {                                       \
        uint32_t af[2][4], bf[8][2];                                           \
        _Pragma("unroll")                                                      \
        for (int mt = 0; mt < 2; mt++) {                                       \
            const int mr = wm + (mt << 4) + g;                                 \
            af[mt][0] = sA[mr * RS + kk + tq];                                 \
            af[mt][1] = sA[(mr + 8) * RS + kk + tq];                           \
            af[mt][2] = sA[mr * RS + kk + tq + 4];                             \
            af[mt][3] = sA[(mr + 8) * RS + kk + tq + 4];                       \
        }                                                                      \
        _Pragma("unroll")                                                      \
        for (int nt8 = 0; nt8 < 8; nt8++) {                                    \
            const int nr = wn + (nt8 << 3) + g;                                \
            bf[nt8][0] = sBp[nr * RS + kk + tq];                               \
            bf[nt8][1] = sBp[nr * RS + kk + tq + 4];                           \
        }                                                                      \
        _Pragma("unroll")                                                      \
        for (int mt = 0; mt < 2; mt++)                                         \
            _Pragma("unroll")                                                  \
            for (int nt8 = 0; nt8 < 8; nt8++)                                  \
                mma_m16n8k8(acc[mt][nt8], af[mt], bf[nt8]);                    \
    }                                                                          \
} while (0)

    ISSUE(0u, 0);        CP_COMMIT();
    ISSUE((uint32_t)SWB, 1); CP_COMMIT();

    int buf = 0;
    for (int t = 0; t < nt; ++t) {
        CP_WAIT1();
        __syncthreads();
        if (t + 2 < nt) {
            int nb = buf + 2; if (nb >= 3) nb -= 3;
            ISSUE((uint32_t)(nb * SWB), t + 2);
        }
        CP_COMMIT();
        COMPUTE(buf);
        buf = (buf == 2) ? 0 : buf + 1;
    }

    // ---------------- epilogue: direct register -> GMEM stores -----------------
#pragma unroll
    for (int mt = 0; mt < 2; mt++) {
#pragma unroll
        for (int nt8 = 0; nt8 < 8; nt8++) {
            const int row = m0 + wm + (mt << 4) + g;
            const int col = n0 + wn + (nt8 << 3) + (tq << 1);
            float2 v0, v1;
            if (round_out) {
                v0.x = f2tff(acc[mt][nt8][0]); v0.y = f2tff(acc[mt][nt8][1]);
                v1.x = f2tff(acc[mt][nt8][2]); v1.y = f2tff(acc[mt][nt8][3]);
            } else {
                v0.x = acc[mt][nt8][0]; v0.y = acc[mt][nt8][1];
                v1.x = acc[mt][nt8][2]; v1.y = acc[mt][nt8][3];
            }
            *(float2*)(C + (size_t)row * ldc + col)       = v0;
            *(float2*)(C + (size_t)(row + 8) * ldc + col) = v1;
        }
    }
#undef ISSUE
#undef COMPUTE
}

// ---------------- tf32 rounding copy ------------------------------------------
__global__ void round_tf(const float4* __restrict__ src, float4* __restrict__ dst)
{
    const size_t i = (size_t)blockIdx.x * 256 + threadIdx.x;
    float4 v = src[i];
    v.x = f2tff(v.x); v.y = f2tff(v.y); v.z = f2tff(v.z); v.w = f2tff(v.w);
    dst[i] = v;
}

// ---------------- RoPE: q rounded in place; k -> xk (full) + kr (rounded);
//                  v -> xv (full) --------------------------------------------
__global__ void rope_scatter(float* __restrict__ q, const float* __restrict__ k,
                             const float* __restrict__ v,
                             const float* __restrict__ rope,
                             float* __restrict__ xk, float* __restrict__ xv,
                             float* __restrict__ kr)
{
    const size_t idx = (size_t)blockIdx.x * 256 + threadIdx.x; // < 4194304
    const int j = (int)(idx & 63);
    const int h = (int)((idx >> 6) & 31);
    const int s = (int)((idx >> 11) & 1023);
    const int b = (int)(idx >> 21);

    const size_t src = ((size_t)(b * SEQ + s)) * DIM + h * HDIM + 2 * j;
    const float c  = rope[(size_t)(s * 64 + j) * 2];
    const float sn = rope[(size_t)(s * 64 + j) * 2 + 1];

    const float q0 = q[src], q1 = q[src + 1];
    q[src]     = f2tff(q0 * c - q1 * sn);
    q[src + 1] = f2tff(q0 * sn + q1 * c);

    const float k0 = k[src], k1 = k[src + 1];
    const float kr0 = k0 * c - k1 * sn;
    const float kr1 = k0 * sn + k1 * c;
    const size_t dst = (((size_t)(b * NHEADS + h)) * TKV + CACHE + s) * HDIM + 2 * j;
    xk[dst]     = kr0;
    xk[dst + 1] = kr1;
    kr[dst]     = f2tff(kr0);
    kr[dst + 1] = f2tff(kr1);

    xv[dst]     = v[src];
    xv[dst + 1] = v[src + 1];
}

// ---------------- copy caches into xk/xv (full) + kr (rounded) ----------------
__global__ void cache_copy(const float* __restrict__ kc,
                           const float* __restrict__ vc,
                           float* __restrict__ xk, float* __restrict__ xv,
                           float* __restrict__ kr)
{
    const size_t i4  = (size_t)blockIdx.x * 256 + threadIdx.x; // < 2097152
    const size_t src = i4 * 4;
    const size_t bh  = src >> 17;              // / (CACHE*HDIM)
    const size_t dst = src + bh * (size_t)(CACHE * HDIM);
    const float4 kv = *(const float4*)(kc + src);
    *(float4*)(xk + dst) = kv;
    float4 kq;
    kq.x = f2tff(kv.x); kq.y = f2tff(kv.y); kq.z = f2tff(kv.z); kq.w = f2tff(kv.w);
    *(float4*)(kr + dst) = kq;
    *(float4*)(xv + dst) = *(const float4*)(vc + src);
}

// ---------------- transpose xv -> vt[b,h,d,t] (rounded) -----------------------
__global__ void transpose_v(const float* __restrict__ xv, float* __restrict__ vt)
{
    __shared__ float tile[32][33];
    const int bh = blockIdx.z;
    const int t0 = blockIdx.x << 5, d0 = blockIdx.y << 5;
    const float* src = xv + (size_t)bh * TKV * HDIM;
    float*       dst = vt + (size_t)bh * HDIM * TKV;
    const int tx = threadIdx.x, ty = threadIdx.y;  // 32 x 8
#pragma unroll
    for (int i = 0; i < 32; i += 8)
        tile[ty + i][tx] = src[(size_t)(t0 + ty + i) * HDIM + d0 + tx];
    __syncthreads();
#pragma unroll
    for (int i = 0; i < 32; i += 8)
        dst[(size_t)(d0 + ty + i) * TKV + t0 + tx] = f2tff(tile[tx][ty + i]);
}

// ---------------- causal softmax (writes rounded probs, capped length) --------
__global__ void softmax_causal(float* __restrict__ S)
{
    const int s  = blockIdx.x;
    const int bh = blockIdx.y;
    float* row = S + ((size_t)bh * SEQ + s) * TKV;
    const int L    = CACHE + s + 1;
    const int capb = CACHE + (s & ~127) + 128;   // PV reads exactly [0, capb)
    const int tid = threadIdx.x;
    const float scale = 0.08838834764831845f; // 1/sqrt(128)

    float v[8];
    float m = -3.0e38f;
#pragma unroll
    for (int i = 0; i < 8; i++) {
        const int idx = tid + (i << 8);
        v[i] = (idx < L) ? row[idx] : -3.0e38f;
        m = fmaxf(m, v[i]);
    }
    __shared__ float red[8];
#pragma unroll
    for (int o = 16; o > 0; o >>= 1) m = fmaxf(m, __shfl_xor_sync(0xffffffffu, m, o));
    if ((tid & 31) == 0) red[tid >> 5] = m;
    __syncthreads();
    float bm = red[0];
#pragma unroll
    for (int i = 1; i < 8; i++) bm = fmaxf(bm, red[i]);

    float sum = 0.f;
#pragma unroll
    for (int i = 0; i < 8; i++) {
        const int idx = tid + (i << 8);
        if (idx < L) { v[i] = __expf(scale * (v[i] - bm)); sum += v[i]; }
        else         { v[i] = 0.f; }
    }
#pragma unroll
    for (int o = 16; o > 0; o >>= 1) sum += __shfl_xor_sync(0xffffffffu, sum, o);
    __syncthreads();
    if ((tid & 31) == 0) red[tid >> 5] = sum;
    __syncthreads();
    float bs = 0.f;
#pragma unroll
    for (int i = 0; i < 8; i++) bs += red[i];
    const float inv = 1.f / bs;
#pragma unroll
    for (int i = 0; i < 8; i++) {
        const int idx = tid + (i << 8);
        if (idx < capb) row[idx] = f2tff(v[i] * inv);
    }
}

// ---------------- launch --------------------------------------------------------
extern "C" void kernel_launch(void* const* d_in, const int* in_sizes, int n_in,
                              void* d_out, int out_size)
{
    const float* x    = (const float*)d_in[0];
    const float* kc   = (const float*)d_in[1];
    const float* vc   = (const float*)d_in[2];
    const float* rope = (const float*)d_in[3];
    const float* Wq   = (const float*)d_in[4];
    const float* Wk   = (const float*)d_in[5];
    const float* Wv   = (const float*)d_in[6];
    const float* Wo   = (const float*)d_in[7];

    float* out = (float*)d_out;
    float* xk  = out + (size_t)BSZ * SEQ * DIM;               // +8388608
    float* xv  = xk + (size_t)BSZ * NHEADS * TKV * HDIM;      // +16777216

    float *xr, *wq, *wk, *wv, *wo, *q, *k, *v, *ctx, *kr, *vt, *sc;
    cudaGetSymbolAddress((void**)&xr,  g_xr);
    cudaGetSymbolAddress((void**)&wq,  g_wq);
    cudaGetSymbolAddress((void**)&wk,  g_wk);
    cudaGetSymbolAddress((void**)&wv,  g_wv);
    cudaGetSymbolAddress((void**)&wo,  g_wo);
    cudaGetSymbolAddress((void**)&q,   g_q);
    cudaGetSymbolAddress((void**)&k,   g_k);
    cudaGetSymbolAddress((void**)&v,   g_v);
    cudaGetSymbolAddress((void**)&ctx, g_ctx);
    cudaGetSymbolAddress((void**)&kr,  g_kr);
    cudaGetSymbolAddress((void**)&vt,  g_vt);
    cudaGetSymbolAddress((void**)&sc,  g_sc);

    static int smem_set = 0;
    const int GSMEM = 3 * 2 * 128 * 36 * 4;   // 110592 bytes
    if (!smem_set) {
        cudaFuncSetAttribute(gemm_tc, cudaFuncAttributeMaxDynamicSharedMemorySize, GSMEM);
        smem_set = 1;
    }

    const dim3 blk(256);

    // Pre-round x and weights to tf32 bits
    round_tf<<<MROWS * DIM / 1024, blk>>>((const float4*)x,  (float4*)xr);
    round_tf<<<DIM * DIM / 1024,   blk>>>((const float4*)Wq, (float4*)wq);
    round_tf<<<DIM * DIM / 1024,   blk>>>((const float4*)Wk, (float4*)wk);
    round_tf<<<DIM * DIM / 1024,   blk>>>((const float4*)Wv, (float4*)wv);
    round_tf<<<DIM * DIM / 1024,   blk>>>((const float4*)Wo, (float4*)wo);

    // Q/K/V projections: C[2048,4096] = xr * W^T   (full precision outputs)
    const dim3 gp(DIM / 128, MROWS / 128, 1);
    gemm_tc<<<gp, blk, GSMEM>>>(xr, wq, q, DIM, DIM, DIM, DIM,
                                0, 0, 0, 0, 0, 0, 1, 0, 0, 0);
    gemm_tc<<<gp, blk, GSMEM>>>(xr, wk, k, DIM, DIM, DIM, DIM,
                                0, 0, 0, 0, 0, 0, 1, 0, 0, 0);
    gemm_tc<<<gp, blk, GSMEM>>>(xr, wv, v, DIM, DIM, DIM, DIM,
                                0, 0, 0, 0, 0, 0, 1, 0, 0, 0);

    cache_copy<<<8192, blk>>>(kc, vc, xk, xv, kr);
    rope_scatter<<<16384, blk>>>(q, k, v, rope, xk, xv, kr);
    transpose_v<<<dim3(TKV / 32, HDIM / 32, BSZ * NHEADS), dim3(32, 8)>>>(xv, vt);

    // scores[b,h,s,t] = q . kr   (NT, K=128, causal block skip)
    const dim3 gs(TKV / 128, SEQ / 128, BSZ * NHEADS);
    gemm_tc<<<gs, blk, GSMEM>>>(
        q, kr, sc, HDIM, DIM, HDIM, TKV,
        (long long)SEQ * DIM, HDIM,
        (long long)NHEADS * TKV * HDIM, (long long)TKV * HDIM,
        (long long)NHEADS * SEQ * TKV, (long long)SEQ * TKV, NHEADS,
        1, 0, 0);

    const dim3 gsm(SEQ, BSZ * NHEADS);
    softmax_causal<<<gsm, blk>>>(sc);

    // ctx = P @ vt^T   (NT, K capped by causal bound, rounded output)
    const dim3 gpv(HDIM / 128, SEQ / 128, BSZ * NHEADS);
    gemm_tc<<<gpv, blk, GSMEM>>>(
        sc, vt, ctx, TKV, TKV, TKV, DIM,
        (long long)NHEADS * SEQ * TKV, (long long)SEQ * TKV,
        (long long)NHEADS * HDIM * TKV, (long long)HDIM * TKV,
        (long long)SEQ * DIM, HDIM, NHEADS,
        0, 1, 1);

    // output = ctx @ Wo^T
    gemm_tc<<<gp, blk, GSMEM>>>(ctx, wo, out, DIM, DIM, DIM, DIM,
                                0, 0, 0, 0, 0, 0, 1, 0, 0, 0);
}

// round 4
// speedup vs baseline: 1.3450x; 1.0389x over previous
#include <cuda_runtime.h>
#include <cstdint>
#include <cstddef>

#define DIM     4096
#define HDIM    128
#define NHEADS  32
#define BSZ     2
#define SEQ     1024
#define CACHE   1024
#define TKV     2048
#define MROWS   2048   // BSZ*SEQ

// ---------------- scratch (static device memory; no allocations allowed) ----
static __device__ float g_xr [(size_t)MROWS * DIM];                 // rounded x
static __device__ float g_wq [(size_t)DIM * DIM];
static __device__ float g_wk [(size_t)DIM * DIM];
static __device__ float g_wv [(size_t)DIM * DIM];
static __device__ float g_wo [(size_t)DIM * DIM];
static __device__ float g_q  [(size_t)MROWS * DIM];
static __device__ float g_k  [(size_t)MROWS * DIM];
static __device__ float g_v  [(size_t)MROWS * DIM];
static __device__ float g_ctx[(size_t)MROWS * DIM];
static __device__ float g_kr [(size_t)BSZ * NHEADS * TKV * HDIM];
static __device__ float g_vt [(size_t)BSZ * NHEADS * HDIM * TKV];
static __device__ float g_sc [(size_t)BSZ * NHEADS * SEQ * TKV];    // 512MB

// ---------------- helpers -----------------------------------------------------
__device__ __forceinline__ uint32_t f2tf(float x) {
    uint32_t r;
    asm("cvt.rna.tf32.f32 %0, %1;" : "=r"(r) : "f"(x));
    return r;
}
__device__ __forceinline__ float f2tff(float x) {
    return __uint_as_float(f2tf(x));
}

__device__ __forceinline__ uint32_t smem_u32(const void* p) {
    uint32_t a;
    asm("{ .reg .u64 t; cvta.to.shared.u64 t, %1; cvt.u32.u64 %0, t; }"
        : "=r"(a) : "l"(p));
    return a;
}

__device__ __forceinline__ void cp16(uint32_t dst, const float* src) {
    asm volatile("cp.async.cg.shared.global [%0], [%1], 16;"
                 :: "r"(dst), "l"(src));
}
#define CP_COMMIT() asm volatile("cp.async.commit_group;" ::: "memory")
#define CP_WAIT1()  asm volatile("cp.async.wait_group 1;"  ::: "memory")

__device__ __forceinline__ void mma_m16n8k8(float c[4], const uint32_t a[4],
                                            const uint32_t b[2]) {
    asm volatile(
        "mma.sync.aligned.m16n8k8.row.col.f32.tf32.tf32.f32 "
        "{%0,%1,%2,%3},{%4,%5,%6,%7},{%8,%9},{%0,%1,%2,%3};\n"
        : "+f"(c[0]), "+f"(c[1]), "+f"(c[2]), "+f"(c[3])
        : "r"(a[0]), "r"(a[1]), "r"(a[2]), "r"(a[3]),
          "r"(b[0]), "r"(b[1]));
}

// ---------------- pipelined TF32 NT GEMM --------------------------------------
// C[M,N] = A[M,K] * B[N,K]^T.  A/B hold tf32-rounded bits (no cvt inside).
// Block tile 128 x NTILE (NTILE = 256 or 128), K-chunk 32, 3-stage cp.async,
// 256 threads = 8 warps arranged 2(M) x 4(N); warp tile 64 x (NTILE/4).
// causal: skip block if n0 >= CACHE + m0 + 128 (scores).
// kcap:   clamp K to CACHE + m0 + 128 (PV; tail of A rows is exact zeros).
// round_out: tf32-round C values at store (internal tensors feeding GEMMs).
template <int NTILE>
__global__ __launch_bounds__(256) void gemm_tc(
    const float* __restrict__ Ag, const float* __restrict__ Bg,
    float* __restrict__ Cg, int K, int lda, int ldb, int ldc,
    long long sAb, long long sAh, long long sBb, long long sBh,
    long long sCb, long long sCh, int nH,
    int causal, int kcap, int round_out)
{
    constexpr int RS  = 36;                   // smem row stride (words)
    constexpr int AW  = 128 * RS;             // A tile words
    constexpr int SW  = (128 + NTILE) * RS;   // stage words
    constexpr int SWB = SW * 4;               // stage bytes
    constexpr int NB  = NTILE / 32;           // B cp16 per thread (8 or 4)
    constexpr int NT  = NTILE / 32;           // B fragments per warp (8 or 4)
    extern __shared__ float smem[];

    const int z  = blockIdx.z;
    const int bb = z / nH, hh = z - bb * nH;
    const float* A = Ag + (size_t)bb * sAb + (size_t)hh * sAh;
    const float* B = Bg + (size_t)bb * sBb + (size_t)hh * sBh;
    float*       C = Cg + (size_t)bb * sCb + (size_t)hh * sCh;
    const int m0 = blockIdx.y << 7;
    const int n0 = blockIdx.x * NTILE;

    if (causal && n0 >= CACHE + m0 + 128) return;
    int Keff = K;
    if (kcap) { const int cap = CACHE + m0 + 128; if (cap < K) Keff = cap; }
    const int nt = Keff >> 5;

    const int tid  = threadIdx.x;
    const int lane = tid & 31, w = tid >> 5;
    const int wm = (w & 1) << 6;              // warp M offset: 0 / 64
    const int wn = (w >> 1) * (NTILE / 4);    // warp N offset
    const int g  = lane >> 2, tq = lane & 3;

    // cp.async mapping: thread covers rows crow+32i, one 16B chunk per row
    const int crow = tid >> 3;                 // 0..31
    const int cch  = (tid & 7) << 2;           // word col 0,4,...,28
    const float* aP = A + (size_t)(m0 + crow) * lda + cch;
    const float* bP = B + (size_t)(n0 + crow) * ldb + cch;
    const uint32_t sb = smem_u32(smem);
    const uint32_t dA = sb + (uint32_t)((crow * RS + cch) << 2);
    const uint32_t dB = sb + (uint32_t)((AW + crow * RS + cch) << 2);

    float acc[4][NT][4];
#pragma unroll
    for (int i = 0; i < 4; i++)
#pragma unroll
        for (int j = 0; j < NT; j++)
#pragma unroll
            for (int l = 0; l < 4; l++) acc[i][j][l] = 0.f;

#define ISSUE(SOFF, T) do {                                                    \
    const int _k0 = (T) << 5;                                                  \
    _Pragma("unroll")                                                          \
    for (int _i = 0; _i < 4; _i++)                                             \
        cp16(dA + (SOFF) + (uint32_t)(_i * (32 * RS * 4)),                     \
             aP + _k0 + (size_t)(_i * 32) * lda);                              \
    _Pragma("unroll")                                                          \
    for (int _i = 0; _i < NB; _i++)                                            \
        cp16(dB + (SOFF) + (uint32_t)(_i * (32 * RS * 4)),                     \
             bP + _k0 + (size_t)(_i * 32) * ldb);                              \
} while (0)

#define COMPUTE(BUF) do {                                                      \
    const uint32_t* sA  = (const uint32_t*)smem + (BUF) * SW;                  \
    const uint32_t* sBp = sA + AW;                                             \
    _Pragma("unroll")                                                          \
    for (int kk = 0; kk < 32; kk += 8) {                                       \
        uint32_t af[4][4], bf[NT][2];                                          \
        _Pragma("unroll")                                                      \
        for (int mt = 0; mt < 4; mt++) {                                       \
            const int mr = wm + (mt << 4) + g;                                 \
            af[mt][0] = sA[mr * RS + kk + tq];                                 \
            af[mt][1] = sA[(mr + 8) * RS + kk + tq];                           \
            af[mt][2] = sA[mr * RS + kk + tq + 4];                             \
            af[mt][3] = sA[(mr + 8) * RS + kk + tq + 4];                       \
        }                                                                      \
        _Pragma("unroll")                                                      \
        for (int nt8 = 0; nt8 < NT; nt8++) {                                   \
            const int nr = wn + (nt8 << 3) + g;                                \
            bf[nt8][0] = sBp[nr * RS + kk + tq];                               \
            bf[nt8][1] = sBp[nr * RS + kk + tq + 4];                           \
        }                                                                      \
        _Pragma("unroll")                                                      \
        for (int mt = 0; mt < 4; mt++)                                         \
            _Pragma("unroll")                                                  \
            for (int nt8 = 0; nt8 < NT; nt8++)                                 \
                mma_m16n8k8(acc[mt][nt8], af[mt], bf[nt8]);                    \
    }                                                                          \
} while (0)

    ISSUE(0u, 0);            CP_COMMIT();
    ISSUE((uint32_t)SWB, 1); CP_COMMIT();

    int buf = 0;
    for (int t = 0; t < nt; ++t) {
        CP_WAIT1();
        __syncthreads();
        if (t + 2 < nt) {
            int nb = buf + 2; if (nb >= 3) nb -= 3;
            ISSUE((uint32_t)(nb * SWB), t + 2);
        }
        CP_COMMIT();
        COMPUTE(buf);
        buf = (buf == 2) ? 0 : buf + 1;
    }

    // ---------------- epilogue: direct register -> GMEM stores -----------------
#pragma unroll
    for (int mt = 0; mt < 4; mt++) {
#pragma unroll
        for (int nt8 = 0; nt8 < NT; nt8++) {
            const int row = m0 + wm + (mt << 4) + g;
            const int col = n0 + wn + (nt8 << 3) + (tq << 1);
            float2 v0, v1;
            if (round_out) {
                v0.x = f2tff(acc[mt][nt8][0]); v0.y = f2tff(acc[mt][nt8][1]);
                v1.x = f2tff(acc[mt][nt8][2]); v1.y = f2tff(acc[mt][nt8][3]);
            } else {
                v0.x = acc[mt][nt8][0]; v0.y = acc[mt][nt8][1];
                v1.x = acc[mt][nt8][2]; v1.y = acc[mt][nt8][3];
            }
            *(float2*)(C + (size_t)row * ldc + col)       = v0;
            *(float2*)(C + (size_t)(row + 8) * ldc + col) = v1;
        }
    }
#undef ISSUE
#undef COMPUTE
}

// ---------------- tf32 rounding copy ------------------------------------------
__global__ void round_tf(const float4* __restrict__ src, float4* __restrict__ dst)
{
    const size_t i = (size_t)blockIdx.x * 256 + threadIdx.x;
    float4 v = src[i];
    v.x = f2tff(v.x); v.y = f2tff(v.y); v.z = f2tff(v.z); v.w = f2tff(v.w);
    dst[i] = v;
}

// ---------------- RoPE: q rounded in place; k -> xk (full) + kr (rounded);
//                  v -> xv (full) --------------------------------------------
__global__ void rope_scatter(float* __restrict__ q, const float* __restrict__ k,
                             const float* __restrict__ v,
                             const float* __restrict__ rope,
                             float* __restrict__ xk, float* __restrict__ xv,
                             float* __restrict__ kr)
{
    const size_t idx = (size_t)blockIdx.x * 256 + threadIdx.x; // < 4194304
    const int j = (int)(idx & 63);
    const int h = (int)((idx >> 6) & 31);
    const int s = (int)((idx >> 11) & 1023);
    const int b = (int)(idx >> 21);

    const size_t src = ((size_t)(b * SEQ + s)) * DIM + h * HDIM + 2 * j;
    const float c  = rope[(size_t)(s * 64 + j) * 2];
    const float sn = rope[(size_t)(s * 64 + j) * 2 + 1];

    const float q0 = q[src], q1 = q[src + 1];
    q[src]     = f2tff(q0 * c - q1 * sn);
    q[src + 1] = f2tff(q0 * sn + q1 * c);

    const float k0 = k[src], k1 = k[src + 1];
    const float kr0 = k0 * c - k1 * sn;
    const float kr1 = k0 * sn + k1 * c;
    const size_t dst = (((size_t)(b * NHEADS + h)) * TKV + CACHE + s) * HDIM + 2 * j;
    xk[dst]     = kr0;
    xk[dst + 1] = kr1;
    kr[dst]     = f2tff(kr0);
    kr[dst + 1] = f2tff(kr1);

    xv[dst]     = v[src];
    xv[dst + 1] = v[src + 1];
}

// ---------------- copy caches into xk/xv (full) + kr (rounded) ----------------
__global__ void cache_copy(const float* __restrict__ kc,
                           const float* __restrict__ vc,
                           float* __restrict__ xk, float* __restrict__ xv,
                           float* __restrict__ kr)
{
    const size_t i4  = (size_t)blockIdx.x * 256 + threadIdx.x; // < 2097152
    const size_t src = i4 * 4;
    const size_t bh  = src >> 17;              // / (CACHE*HDIM)
    const size_t dst = src + bh * (size_t)(CACHE * HDIM);
    const float4 kv = *(const float4*)(kc + src);
    *(float4*)(xk + dst) = kv;
    float4 kq;
    kq.x = f2tff(kv.x); kq.y = f2tff(kv.y); kq.z = f2tff(kv.z); kq.w = f2tff(kv.w);
    *(float4*)(kr + dst) = kq;
    *(float4*)(xv + dst) = *(const float4*)(vc + src);
}

// ---------------- transpose xv -> vt[b,h,d,t] (rounded) -----------------------
__global__ void transpose_v(const float* __restrict__ xv, float* __restrict__ vt)
{
    __shared__ float tile[32][33];
    const int bh = blockIdx.z;
    const int t0 = blockIdx.x << 5, d0 = blockIdx.y << 5;
    const float* src = xv + (size_t)bh * TKV * HDIM;
    float*       dst = vt + (size_t)bh * HDIM * TKV;
    const int tx = threadIdx.x, ty = threadIdx.y;  // 32 x 8
#pragma unroll
    for (int i = 0; i < 32; i += 8)
        tile[ty + i][tx] = src[(size_t)(t0 + ty + i) * HDIM + d0 + tx];
    __syncthreads();
#pragma unroll
    for (int i = 0; i < 32; i += 8)
        dst[(size_t)(d0 + ty + i) * TKV + t0 + tx] = f2tff(tile[tx][ty + i]);
}

// ---------------- causal softmax (writes rounded probs, capped length) --------
__global__ void softmax_causal(float* __restrict__ S)
{
    const int s  = blockIdx.x;
    const int bh = blockIdx.y;
    float* row = S + ((size_t)bh * SEQ + s) * TKV;
    const int L    = CACHE + s + 1;
    const int capb = CACHE + (s & ~127) + 128;   // PV reads exactly [0, capb)
    const int tid = threadIdx.x;
    const float scale = 0.08838834764831845f; // 1/sqrt(128)

    float v[8];
    float m = -3.0e38f;
#pragma unroll
    for (int i = 0; i < 8; i++) {
        const int idx = tid + (i << 8);
        v[i] = (idx < L) ? row[idx] : -3.0e38f;
        m = fmaxf(m, v[i]);
    }
    __shared__ float red[8];
#pragma unroll
    for (int o = 16; o > 0; o >>= 1) m = fmaxf(m, __shfl_xor_sync(0xffffffffu, m, o));
    if ((tid & 31) == 0) red[tid >> 5] = m;
    __syncthreads();
    float bm = red[0];
#pragma unroll
    for (int i = 1; i < 8; i++) bm = fmaxf(bm, red[i]);

    float sum = 0.f;
#pragma unroll
    for (int i = 0; i < 8; i++) {
        const int idx = tid + (i << 8);
        if (idx < L) { v[i] = __expf(scale * (v[i] - bm)); sum += v[i]; }
        else         { v[i] = 0.f; }
    }
#pragma unroll
    for (int o = 16; o > 0; o >>= 1) sum += __shfl_xor_sync(0xffffffffu, sum, o);
    __syncthreads();
    if ((tid & 31) == 0) red[tid >> 5] = sum;
    __syncthreads();
    float bs = 0.f;
#pragma unroll
    for (int i = 0; i < 8; i++) bs += red[i];
    const float inv = 1.f / bs;
#pragma unroll
    for (int i = 0; i < 8; i++) {
        const int idx = tid + (i << 8);
        if (idx < capb) row[idx] = f2tff(v[i] * inv);
    }
}

// ---------------- launch --------------------------------------------------------
extern "C" void kernel_launch(void* const* d_in, const int* in_sizes, int n_in,
                              void* d_out, int out_size)
{
    const float* x    = (const float*)d_in[0];
    const float* kc   = (const float*)d_in[1];
    const float* vc   = (const float*)d_in[2];
    const float* rope = (const float*)d_in[3];
    const float* Wq   = (const float*)d_in[4];
    const float* Wk   = (const float*)d_in[5];
    const float* Wv   = (const float*)d_in[6];
    const float* Wo   = (const float*)d_in[7];

    float* out = (float*)d_out;
    float* xk  = out + (size_t)BSZ * SEQ * DIM;               // +8388608
    float* xv  = xk + (size_t)BSZ * NHEADS * TKV * HDIM;      // +16777216

    float *xr, *wq, *wk, *wv, *wo, *q, *k, *v, *ctx, *kr, *vt, *sc;
    cudaGetSymbolAddress((void**)&xr,  g_xr);
    cudaGetSymbolAddress((void**)&wq,  g_wq);
    cudaGetSymbolAddress((void**)&wk,  g_wk);
    cudaGetSymbolAddress((void**)&wv,  g_wv);
    cudaGetSymbolAddress((void**)&wo,  g_wo);
    cudaGetSymbolAddress((void**)&q,   g_q);
    cudaGetSymbolAddress((void**)&k,   g_k);
    cudaGetSymbolAddress((void**)&v,   g_v);
    cudaGetSymbolAddress((void**)&ctx, g_ctx);
    cudaGetSymbolAddress((void**)&kr,  g_kr);
    cudaGetSymbolAddress((void**)&vt,  g_vt);
    cudaGetSymbolAddress((void**)&sc,  g_sc);

    const int GSMEM256 = 3 * (128 + 256) * 36 * 4;   // 165888 bytes
    const int GSMEM128 = 3 * (128 + 128) * 36 * 4;   // 110592 bytes
    static int smem_set = 0;
    if (!smem_set) {
        cudaFuncSetAttribute(gemm_tc<256>, cudaFuncAttributeMaxDynamicSharedMemorySize, GSMEM256);
        cudaFuncSetAttribute(gemm_tc<128>, cudaFuncAttributeMaxDynamicSharedMemorySize, GSMEM128);
        smem_set = 1;
    }

    const dim3 blk(256);

    // Pre-round x and weights to tf32 bits
    round_tf<<<MROWS * DIM / 1024, blk>>>((const float4*)x,  (float4*)xr);
    round_tf<<<DIM * DIM / 1024,   blk>>>((const float4*)Wq, (float4*)wq);
    round_tf<<<DIM * DIM / 1024,   blk>>>((const float4*)Wk, (float4*)wk);
    round_tf<<<DIM * DIM / 1024,   blk>>>((const float4*)Wv, (float4*)wv);
    round_tf<<<DIM * DIM / 1024,   blk>>>((const float4*)Wo, (float4*)wo);

    // Q/K/V projections: C[2048,4096] = xr * W^T   (full precision outputs)
    const dim3 gp(DIM / 256, MROWS / 128, 1);
    gemm_tc<256><<<gp, blk, GSMEM256>>>(xr, wq, q, DIM, DIM, DIM, DIM,
                                        0, 0, 0, 0, 0, 0, 1, 0, 0, 0);
    gemm_tc<256><<<gp, blk, GSMEM256>>>(xr, wk, k, DIM, DIM, DIM, DIM,
                                        0, 0, 0, 0, 0, 0, 1, 0, 0, 0);
    gemm_tc<256><<<gp, blk, GSMEM256>>>(xr, wv, v, DIM, DIM, DIM, DIM,
                                        0, 0, 0, 0, 0, 0, 1, 0, 0, 0);

    cache_copy<<<8192, blk>>>(kc, vc, xk, xv, kr);
    rope_scatter<<<16384, blk>>>(q, k, v, rope, xk, xv, kr);
    transpose_v<<<dim3(TKV / 32, HDIM / 32, BSZ * NHEADS), dim3(32, 8)>>>(xv, vt);

    // scores[b,h,s,t] = q . kr   (NT, K=128, causal block skip)
    const dim3 gs(TKV / 256, SEQ / 128, BSZ * NHEADS);
    gemm_tc<256><<<gs, blk, GSMEM256>>>(
        q, kr, sc, HDIM, DIM, HDIM, TKV,
        (long long)SEQ * DIM, HDIM,
        (long long)NHEADS * TKV * HDIM, (long long)TKV * HDIM,
        (long long)NHEADS * SEQ * TKV, (long long)SEQ * TKV, NHEADS,
        1, 0, 0);

    const dim3 gsm(SEQ, BSZ * NHEADS);
    softmax_causal<<<gsm, blk>>>(sc);

    // ctx = P @ vt^T   (NT, K capped by causal bound, rounded output)
    const dim3 gpv(HDIM / 128, SEQ / 128, BSZ * NHEADS);
    gemm_tc<128><<<gpv, blk, GSMEM128>>>(
        sc, vt, ctx, TKV, TKV, TKV, DIM,
        (long long)NHEADS * SEQ * TKV, (long long)SEQ * TKV,
        (long long)NHEADS * HDIM * TKV, (long long)HDIM * TKV,
        (long long)SEQ * DIM, HDIM, NHEADS,
        0, 1, 1);

    // output = ctx @ Wo^T
    gemm_tc<256><<<gp, blk, GSMEM256>>>(ctx, wo, out, DIM, DIM, DIM, DIM,
                                        0, 0, 0, 0, 0, 0, 1, 0, 0, 0);
}